// round 14
// baseline (speedup 1.0000x reference)
#include <cuda_runtime.h>
#include <cuda_bf16.h>
#include <cstdint>
#include <math.h>

#define EPS 1e-5f

constexpr int BATCH = 32;
constexpr int S = 1024;
constexpr int D = 1024;

constexpr int PAD = 40;                       // bf16 per smem row (80B stride)
constexpr int ARR_BYTES   = 128 * PAD * 2;    // 10240 B per operand array
constexpr int STAGE_BYTES = 4 * ARR_BYTES;    // 40960 B (Ahi,Alo,Bhi,Blo)
constexpr int NSTAGE = 2;
constexpr int SMEM_DYN = NSTAGE * STAGE_BYTES;  // 81920 B -> 2 CTAs/SM fit

constexpr int N8X = BATCH * S * D / 8;   // 4194304
constexpr int N8W = D * D / 8;           // 131072

// ---------------------------------------------------------------------------
// Global scratch (allocation-free -> __device__ globals), bf16 hi/lo pairs.
// ONLY referenced from device code (R4/R5 bug: symbols passed as kernel args).
// ---------------------------------------------------------------------------
__device__ __align__(16) __nv_bfloat16 g_xhi[(size_t)BATCH * S * D];
__device__ __align__(16) __nv_bfloat16 g_xlo[(size_t)BATCH * S * D];
__device__ __align__(16) __nv_bfloat16 g_Whi[(size_t)D * D];
__device__ __align__(16) __nv_bfloat16 g_Wlo[(size_t)D * D];
__device__ __align__(16) __nv_bfloat16 g_xthi[(size_t)BATCH * S * D];   // xtran
__device__ __align__(16) __nv_bfloat16 g_xtlo[(size_t)BATCH * S * D];
__device__ __align__(16) __nv_bfloat16 g_whi[(size_t)BATCH * S * S];    // weights
__device__ __align__(16) __nv_bfloat16 g_wlo[(size_t)BATCH * S * S];
__device__ __align__(16) __nv_bfloat16 g_xThi[(size_t)BATCH * S * D];   // x^T
__device__ __align__(16) __nv_bfloat16 g_xTlo[(size_t)BATCH * S * D];
__device__ float g_rowsum[BATCH * S];

// ---------------------------------------------------------------------------
// helpers
// ---------------------------------------------------------------------------
__device__ __forceinline__ uint32_t smem_u32(const void* p) {
    uint32_t a;
    asm("{ .reg .u64 t; cvta.to.shared.u64 t, %1; cvt.u32.u64 %0, t; }" : "=r"(a) : "l"(p));
    return a;
}

__device__ __forceinline__ void cp16(uint32_t dst, const void* src) {
    asm volatile("cp.async.cg.shared.global [%0], [%1], 16;" :: "r"(dst), "l"(src) : "memory");
}
#define CP_COMMIT() asm volatile("cp.async.commit_group;" ::: "memory")
#define CP_WAIT1()  asm volatile("cp.async.wait_group 1;" ::: "memory")

__device__ __forceinline__ void ldsm4(uint32_t& r0, uint32_t& r1, uint32_t& r2, uint32_t& r3,
                                      uint32_t addr) {
    asm volatile("ldmatrix.sync.aligned.m8n8.x4.shared.b16 {%0,%1,%2,%3}, [%4];"
                 : "=r"(r0), "=r"(r1), "=r"(r2), "=r"(r3) : "r"(addr));
}

__device__ __forceinline__ void mma_bf16(float* c, const uint32_t* a, const uint32_t* b) {
    asm volatile(
        "mma.sync.aligned.m16n8k16.row.col.f32.bf16.bf16.f32 "
        "{%0,%1,%2,%3}, {%4,%5,%6,%7}, {%8,%9}, {%0,%1,%2,%3};"
        : "+f"(c[0]), "+f"(c[1]), "+f"(c[2]), "+f"(c[3])
        : "r"(a[0]), "r"(a[1]), "r"(a[2]), "r"(a[3]), "r"(b[0]), "r"(b[1]));
}

__device__ __forceinline__ void ld8(const float* __restrict__ p, float* d) {
    float4 v0 = *(const float4*)p;
    float4 v1 = *(const float4*)(p + 4);
    d[0] = v0.x; d[1] = v0.y; d[2] = v0.z; d[3] = v0.w;
    d[4] = v1.x; d[5] = v1.y; d[6] = v1.z; d[7] = v1.w;
}

// fp32[8] -> bf16 hi[8], lo[8].  hi = rn(x); lo = rn(x - hi).
__device__ __forceinline__ void split8(const float* f, __nv_bfloat16* hi, __nv_bfloat16* lo) {
    uint32_t hw[4], lw[4];
#pragma unroll
    for (int i = 0; i < 4; i++) {
        float a = f[2 * i], b = f[2 * i + 1];
        uint32_t h;
        asm("cvt.rn.bf16x2.f32 %0, %1, %2;" : "=r"(h) : "f"(b), "f"(a));
        float ha = __uint_as_float(h << 16);
        float hb = __uint_as_float(h & 0xFFFF0000u);
        uint32_t l;
        asm("cvt.rn.bf16x2.f32 %0, %1, %2;" : "=r"(l) : "f"(b - hb), "f"(a - ha));
        hw[i] = h; lw[i] = l;
    }
    *(uint4*)hi = make_uint4(hw[0], hw[1], hw[2], hw[3]);
    *(uint4*)lo = make_uint4(lw[0], lw[1], lw[2], lw[3]);
}

__device__ __forceinline__ void store_pair_split(__nv_bfloat16* hiP, __nv_bfloat16* loP,
                                                 float v0, float v1) {
    uint32_t h;
    asm("cvt.rn.bf16x2.f32 %0, %1, %2;" : "=r"(h) : "f"(v1), "f"(v0));
    float h0 = __uint_as_float(h << 16);
    float h1 = __uint_as_float(h & 0xFFFF0000u);
    uint32_t l;
    asm("cvt.rn.bf16x2.f32 %0, %1, %2;" : "=r"(l) : "f"(v1 - h1), "f"(v0 - h0));
    *(uint32_t*)hiP = h;
    *(uint32_t*)loP = l;
}

// ---------------------------------------------------------------------------
// MMA block: one K=32 smem stage -> 96 HMMA per warp (3-term bf16 split)
// ---------------------------------------------------------------------------
__device__ __forceinline__ void mma_block(uint32_t base, uint32_t aOff, uint32_t bOff,
                                          float acc[4][4][4]) {
    const uint32_t aHi = base;
    const uint32_t aLo = base + ARR_BYTES;
    const uint32_t bHi = base + 2 * ARR_BYTES;
    const uint32_t bLo = base + 3 * ARR_BYTES;
#pragma unroll
    for (int ks = 0; ks < 2; ks++) {
        const uint32_t koff = ks * 32;   // 16 bf16 = 32B
        uint32_t ah[4][4], al[4][4], bhf[4][2], blf[4][2];

#pragma unroll
        for (int mf = 0; mf < 4; mf++)
            ldsm4(ah[mf][0], ah[mf][1], ah[mf][2], ah[mf][3],
                  aHi + aOff + mf * (16 * PAD * 2) + koff);
#pragma unroll
        for (int p = 0; p < 2; p++) {
            uint32_t r0, r1, r2, r3;
            ldsm4(r0, r1, r2, r3, bHi + bOff + p * (16 * PAD * 2) + koff);
            bhf[2 * p][0] = r0; bhf[2 * p][1] = r2;
            bhf[2 * p + 1][0] = r1; bhf[2 * p + 1][1] = r3;
        }
#pragma unroll
        for (int mf = 0; mf < 4; mf++)
#pragma unroll
            for (int nf = 0; nf < 4; nf++)
                mma_bf16(acc[mf][nf], ah[mf], bhf[nf]);

#pragma unroll
        for (int p = 0; p < 2; p++) {
            uint32_t r0, r1, r2, r3;
            ldsm4(r0, r1, r2, r3, bLo + bOff + p * (16 * PAD * 2) + koff);
            blf[2 * p][0] = r0; blf[2 * p][1] = r2;
            blf[2 * p + 1][0] = r1; blf[2 * p + 1][1] = r3;
        }
#pragma unroll
        for (int mf = 0; mf < 4; mf++)
#pragma unroll
            for (int nf = 0; nf < 4; nf++)
                mma_bf16(acc[mf][nf], ah[mf], blf[nf]);

#pragma unroll
        for (int mf = 0; mf < 4; mf++)
            ldsm4(al[mf][0], al[mf][1], al[mf][2], al[mf][3],
                  aLo + aOff + mf * (16 * PAD * 2) + koff);
#pragma unroll
        for (int mf = 0; mf < 4; mf++)
#pragma unroll
            for (int nf = 0; nf < 4; nf++)
                mma_bf16(acc[mf][nf], al[mf], bhf[nf]);
    }
}

// ---------------------------------------------------------------------------
// Mainloop: acc += A[128,1024] * B[128,1024]^T, pre-split bf16 in gmem,
// 2-stage cp.async pipeline. Write mapping is bank-conflict-free: a 128B
// store phase spans 8 distinct rows (banks r*20 mod 32 all distinct).
// ---------------------------------------------------------------------------
__device__ __forceinline__ void mma_mainloop(const __nv_bfloat16* __restrict__ Ahi,
                                             const __nv_bfloat16* __restrict__ Alo,
                                             const __nv_bfloat16* __restrict__ Bhi,
                                             const __nv_bfloat16* __restrict__ Blo,
                                             float acc[4][4][4]) {
    extern __shared__ __align__(16) char sbuf[];
    const int tid = threadIdx.x;
    const int lane = tid & 31;
    const int wid = tid >> 5;
    const int wm = wid & 1;
    const int wn = wid >> 1;

#pragma unroll
    for (int i = 0; i < 4; i++)
#pragma unroll
        for (int j = 0; j < 4; j++)
#pragma unroll
            for (int k = 0; k < 4; k++) acc[i][j][k] = 0.f;

    const uint32_t sb = smem_u32(sbuf);
    const __nv_bfloat16* srcs[4] = {Ahi, Alo, Bhi, Blo};

    // copy assignment: thread covers row r (0..127), chunks cb and cb+1.
    // Consecutive lanes hit consecutive rows -> conflict-free STS phases.
    const int r  = tid & 127;
    const int cb = (tid >> 7) << 1;        // 0 or 2
    const uint32_t s0 = (uint32_t)(r * (PAD * 2) + cb * 16);
    const uint32_t s1 = s0 + 16;
    const size_t o0 = (size_t)r * 1024 + cb * 8;
    const size_t o1 = o0 + 8;

    auto copy_stage = [&](int slot, int k0) {
        uint32_t base = sb + slot * STAGE_BYTES;
#pragma unroll
        for (int a = 0; a < 4; a++) {
            cp16(base + a * ARR_BYTES + s0, srcs[a] + o0 + k0);
            cp16(base + a * ARR_BYTES + s1, srcs[a] + o1 + k0);
        }
    };

    copy_stage(0, 0);  CP_COMMIT();
    copy_stage(1, 32); CP_COMMIT();

    const int row16 = lane & 15;
    const int c8 = (lane >> 4) * 8;
    const uint32_t aOff = (uint32_t)((wm * 64 + row16) * (PAD * 2) + c8 * 2);
    const uint32_t bOff = (uint32_t)((wn * 32 + row16) * (PAD * 2) + c8 * 2);

    for (int ko = 0; ko < 32; ko++) {
        CP_WAIT1();            // group ko landed
        __syncthreads();       // all warps see stage ko
        mma_block(sb + (ko & 1) * STAGE_BYTES, aOff, bOff, acc);
        __syncthreads();       // all warps done reading slot ko&1
        if (ko + 2 < 32) copy_stage(ko & 1, (ko + 2) * 32);
        CP_COMMIT();           // keep group count exact
    }
}

// ---------------------------------------------------------------------------
// Pre-pass: split x and W into bf16 hi/lo (globals referenced from device code)
// ---------------------------------------------------------------------------
__global__ __launch_bounds__(256)
void conv_split_all_kernel(const float* __restrict__ x, const float* __restrict__ W) {
    size_t idx = (size_t)blockIdx.x * 256 + threadIdx.x;
    if (idx < (size_t)N8X) {
        float f[8];
        ld8(x + idx * 8, f);
        split8(f, g_xhi + idx * 8, g_xlo + idx * 8);
    } else if (idx < (size_t)(N8X + N8W)) {
        size_t j = idx - N8X;
        float f[8];
        ld8(W + j * 8, f);
        split8(f, g_Whi + j * 8, g_Wlo + j * 8);
    }
}

// ---------------------------------------------------------------------------
// Transpose + split: g_xT{hi,lo}[b][d][t] = split(x[b][t][d])
// ---------------------------------------------------------------------------
__global__ __launch_bounds__(256)
void transpose_split_kernel(const float* __restrict__ X) {
    __shared__ float tile[32][33];
    int b = blockIdx.z;
    int t0 = blockIdx.x * 32;
    int d0 = blockIdx.y * 32;
    const float* src = X + (size_t)b * S * D;
    int tx = threadIdx.x & 31, ty = threadIdx.x >> 5;
#pragma unroll
    for (int i = 0; i < 32; i += 8)
        tile[ty + i][tx] = src[(size_t)(t0 + ty + i) * D + d0 + tx];
    __syncthreads();

    int half = tx >> 4;        // 0: write hi, 1: write lo
    int k = tx & 15;           // t-pair index
#pragma unroll
    for (int i = 0; i < 32; i += 8) {
        int d = ty + i;
        float v0 = tile[2 * k][d], v1 = tile[2 * k + 1][d];
        uint32_t h;
        asm("cvt.rn.bf16x2.f32 %0, %1, %2;" : "=r"(h) : "f"(v1), "f"(v0));
        size_t off = (size_t)b * S * D + (size_t)(d0 + d) * 1024 + t0 + 2 * k;
        if (half == 0) {
            *(uint32_t*)&g_xThi[off] = h;
        } else {
            float h0 = __uint_as_float(h << 16);
            float h1 = __uint_as_float(h & 0xFFFF0000u);
            uint32_t l;
            asm("cvt.rn.bf16x2.f32 %0, %1, %2;" : "=r"(l) : "f"(v1 - h1), "f"(v0 - h0));
            *(uint32_t*)&g_xTlo[off] = l;
        }
    }
}

// ---------------------------------------------------------------------------
// GEMM1: xtran = x @ W^T + bias -> split bf16 hi/lo
// ---------------------------------------------------------------------------
__global__ __launch_bounds__(256, 2)
void gemm1_kernel(const float* __restrict__ bias) {
    const int m0 = blockIdx.y * 128;
    const int n0 = blockIdx.x * 128;

    float acc[4][4][4];
    mma_mainloop(g_xhi + (size_t)m0 * 1024, g_xlo + (size_t)m0 * 1024,
                 g_Whi + (size_t)n0 * 1024, g_Wlo + (size_t)n0 * 1024, acc);

    const int lane = threadIdx.x & 31, wid = threadIdx.x >> 5;
    const int wm = wid & 1, wn = wid >> 1;

#pragma unroll
    for (int mf = 0; mf < 4; mf++)
#pragma unroll
        for (int nf = 0; nf < 4; nf++) {
            int col = n0 + wn * 32 + nf * 8 + (lane & 3) * 2;
            float b0 = __ldg(&bias[col]), b1 = __ldg(&bias[col + 1]);
#pragma unroll
            for (int h = 0; h < 2; h++) {
                int row = m0 + wm * 64 + mf * 16 + (lane >> 2) + h * 8;
                size_t off = (size_t)row * 1024 + col;
                store_pair_split(&g_xthi[off], &g_xtlo[off],
                                 acc[mf][nf][h * 2 + 0] + b0,
                                 acc[mf][nf][h * 2 + 1] + b1);
            }
        }
}

// ---------------------------------------------------------------------------
// GEMM2: weights[b] = xtran[b] @ x[b]^T + decay/opinion/exp(tanh)/mask epilogue
// ---------------------------------------------------------------------------
__global__ __launch_bounds__(256, 2)
void gemm2_kernel(const float* __restrict__ go, const float* __restrict__ po,
                  const float* __restrict__ gprob) {
    const int b  = blockIdx.z;
    const int m0 = blockIdx.y * 128;
    const int n0 = blockIdx.x * 128;

    float acc[4][4][4];
    mma_mainloop(g_xthi + ((size_t)b * S + m0) * 1024, g_xtlo + ((size_t)b * S + m0) * 1024,
                 g_xhi  + ((size_t)b * S + n0) * 1024, g_xlo  + ((size_t)b * S + n0) * 1024, acc);

    const int lane = threadIdx.x & 31, wid = threadIdx.x >> 5;
    const int wm = wid & 1, wn = wid >> 1;
    const float gp = __ldg(gprob);

#pragma unroll
    for (int mf = 0; mf < 4; mf++) {
#pragma unroll
        for (int h = 0; h < 2; h++) {
            int s = m0 + wm * 64 + mf * 16 + (lane >> 2) + h * 8;
            const float* goP = go + ((size_t)b * S + s) * 5;
            const float* poP = po + ((size_t)b * S + s) * 5;
            float ow = gp * (__ldg(&goP[1]) + __ldg(&goP[2])) +
                       (1.f - gp) * (__ldg(&poP[3]) + __ldg(&poP[4]));
#pragma unroll
            for (int nf = 0; nf < 4; nf++) {
                int t0 = n0 + wn * 32 + nf * 8 + (lane & 3) * 2;
                float v[2];
#pragma unroll
                for (int j = 0; j < 2; j++) {
                    int t = t0 + j;
                    float w = acc[mf][nf][h * 2 + j] * ow;
                    float loc = fabsf((float)(s - t));
                    w = __fdividef(w, loc + EPS);
                    float e2 = __expf(2.f * w);
                    float th = 1.f - __fdividef(2.f, e2 + 1.f);
                    float r = __expf(th);
                    if (s == t) r = 0.f;
                    v[j] = r;
                }
                size_t off = ((size_t)b * S + s) * S + t0;
                store_pair_split(&g_whi[off], &g_wlo[off], v[0], v[1]);
            }
        }
    }
}

// ---------------------------------------------------------------------------
// Rowsum over weights rows (reads hi+lo)
// ---------------------------------------------------------------------------
__device__ __forceinline__ float sum_bf2(uint32_t u) {
    __nv_bfloat162 v = *reinterpret_cast<__nv_bfloat162*>(&u);
    float2 f = __bfloat1622float2(v);
    return f.x + f.y;
}

__global__ __launch_bounds__(256)
void rowsum_kernel() {
    const size_t row = blockIdx.x;
    const __nv_bfloat16* ph = g_whi + row * 1024;
    const __nv_bfloat16* pl = g_wlo + row * 1024;
    const int tid = threadIdx.x;

    uint2 uh = *(const uint2*)(ph + tid * 4);
    uint2 ul = *(const uint2*)(pl + tid * 4);
    float s = sum_bf2(uh.x) + sum_bf2(uh.y) + sum_bf2(ul.x) + sum_bf2(ul.y);

#pragma unroll
    for (int off = 16; off > 0; off >>= 1)
        s += __shfl_down_sync(0xFFFFFFFFu, s, off);

    __shared__ float warpsum[8];
    if ((tid & 31) == 0) warpsum[tid >> 5] = s;
    __syncthreads();
    if (tid < 8) {
        float t = warpsum[tid];
#pragma unroll
        for (int off = 4; off > 0; off >>= 1)
            t += __shfl_down_sync(0xFFu, t, off);
        if (tid == 0) g_rowsum[row] = t;
    }
}

// ---------------------------------------------------------------------------
// GEMM3: out[b] = (weights[b] / rowsum) @ x[b]   (B = xT hi/lo)
// ---------------------------------------------------------------------------
__global__ __launch_bounds__(256, 2)
void gemm3_kernel(float* __restrict__ out) {
    const int b  = blockIdx.z;
    const int m0 = blockIdx.y * 128;
    const int n0 = blockIdx.x * 128;

    float acc[4][4][4];
    mma_mainloop(g_whi  + ((size_t)b * S + m0) * 1024, g_wlo  + ((size_t)b * S + m0) * 1024,
                 g_xThi + ((size_t)b * D + n0) * 1024, g_xTlo + ((size_t)b * D + n0) * 1024, acc);

    const int lane = threadIdx.x & 31, wid = threadIdx.x >> 5;
    const int wm = wid & 1, wn = wid >> 1;
    float* Cb = out + (size_t)b * S * D;

#pragma unroll
    for (int mf = 0; mf < 4; mf++)
#pragma unroll
        for (int h = 0; h < 2; h++) {
            int s = m0 + wm * 64 + mf * 16 + (lane >> 2) + h * 8;
            float sc = 1.f / (g_rowsum[b * S + s] + EPS);
#pragma unroll
            for (int nf = 0; nf < 4; nf++) {
                int c0 = n0 + wn * 32 + nf * 8 + (lane & 3) * 2;
                float2 v = make_float2(acc[mf][nf][h * 2 + 0] * sc,
                                       acc[mf][nf][h * 2 + 1] * sc);
                *(float2*)&Cb[(size_t)s * 1024 + c0] = v;
            }
        }
}

// ---------------------------------------------------------------------------
extern "C" void kernel_launch(void* const* d_in, const int* in_sizes, int n_in,
                              void* d_out, int out_size)
{
    const float* x     = (const float*)d_in[0];  // [32,1024,1024]
    const float* W     = (const float*)d_in[1];  // [1024,1024]
    const float* bias  = (const float*)d_in[2];  // [1024]
    const float* go    = (const float*)d_in[3];  // [32,1024,5]
    const float* po    = (const float*)d_in[4];  // [32,1024,5]
    const float* gprob = (const float*)d_in[5];  // scalar
    float* out = (float*)d_out;

    cudaFuncSetAttribute(gemm1_kernel, cudaFuncAttributeMaxDynamicSharedMemorySize, SMEM_DYN);
    cudaFuncSetAttribute(gemm2_kernel, cudaFuncAttributeMaxDynamicSharedMemorySize, SMEM_DYN);
    cudaFuncSetAttribute(gemm3_kernel, cudaFuncAttributeMaxDynamicSharedMemorySize, SMEM_DYN);

    const int nConv = (N8X + N8W) / 256;   // 16896 blocks

    // Launch order chosen so ncu's captured launch (#4) is gemm2_kernel.
    conv_split_all_kernel<<<nConv, 256>>>(x, W);                        // 1
    transpose_split_kernel<<<dim3(32, 32, BATCH), 256>>>(x);            // 2
    gemm1_kernel<<<dim3(8, 256), 256, SMEM_DYN>>>(bias);                // 3
    gemm2_kernel<<<dim3(8, 8, BATCH), 256, SMEM_DYN>>>(go, po, gprob);  // 4  <- profiled
    rowsum_kernel<<<dim3(BATCH * S), 256>>>();                          // 5
    gemm3_kernel<<<dim3(8, 8, BATCH), 256, SMEM_DYN>>>(out);            // 6
}

// round 15
// speedup vs baseline: 1.5168x; 1.5168x over previous
#include <cuda_runtime.h>
#include <cuda_bf16.h>
#include <cstdint>
#include <math.h>

#define EPS 1e-5f

constexpr int BATCH = 32;
constexpr int S = 1024;
constexpr int D = 1024;

constexpr int ROWB = 64;                      // bytes per smem row (K=32 bf16, no pad)
constexpr int ARR_BYTES   = 128 * ROWB;       // 8192 B per operand array
constexpr int STAGE_BYTES = 4 * ARR_BYTES;    // 32768 B (Ahi,Alo,Bhi,Blo)
constexpr int NSTAGE = 2;
constexpr int SMEM_DYN = NSTAGE * STAGE_BYTES;  // 65536 B -> 2 CTAs/SM easily

constexpr int N8X = BATCH * S * D / 8;   // 4194304
constexpr int N8W = D * D / 8;           // 131072

// ---------------------------------------------------------------------------
// Global scratch (allocation-free -> __device__ globals), bf16 hi/lo pairs.
// ONLY referenced from device code (R4/R5 bug: symbols passed as kernel args).
// ---------------------------------------------------------------------------
__device__ __align__(16) __nv_bfloat16 g_xhi[(size_t)BATCH * S * D];
__device__ __align__(16) __nv_bfloat16 g_xlo[(size_t)BATCH * S * D];
__device__ __align__(16) __nv_bfloat16 g_Whi[(size_t)D * D];
__device__ __align__(16) __nv_bfloat16 g_Wlo[(size_t)D * D];
__device__ __align__(16) __nv_bfloat16 g_xthi[(size_t)BATCH * S * D];   // xtran
__device__ __align__(16) __nv_bfloat16 g_xtlo[(size_t)BATCH * S * D];
__device__ __align__(16) __nv_bfloat16 g_whi[(size_t)BATCH * S * S];    // weights
__device__ __align__(16) __nv_bfloat16 g_wlo[(size_t)BATCH * S * S];
__device__ __align__(16) __nv_bfloat16 g_xThi[(size_t)BATCH * S * D];   // x^T
__device__ __align__(16) __nv_bfloat16 g_xTlo[(size_t)BATCH * S * D];
__device__ float g_rowsum[BATCH * S];

// ---------------------------------------------------------------------------
// helpers
// ---------------------------------------------------------------------------
__device__ __forceinline__ uint32_t smem_u32(const void* p) {
    uint32_t a;
    asm("{ .reg .u64 t; cvta.to.shared.u64 t, %1; cvt.u32.u64 %0, t; }" : "=r"(a) : "l"(p));
    return a;
}

__device__ __forceinline__ void cp16(uint32_t dst, const void* src) {
    asm volatile("cp.async.cg.shared.global [%0], [%1], 16;" :: "r"(dst), "l"(src) : "memory");
}
#define CP_COMMIT() asm volatile("cp.async.commit_group;" ::: "memory")
#define CP_WAIT1()  asm volatile("cp.async.wait_group 1;" ::: "memory")

__device__ __forceinline__ void ldsm4(uint32_t& r0, uint32_t& r1, uint32_t& r2, uint32_t& r3,
                                      uint32_t addr) {
    asm volatile("ldmatrix.sync.aligned.m8n8.x4.shared.b16 {%0,%1,%2,%3}, [%4];"
                 : "=r"(r0), "=r"(r1), "=r"(r2), "=r"(r3) : "r"(addr));
}

__device__ __forceinline__ void mma_bf16(float* c, const uint32_t* a, const uint32_t* b) {
    asm volatile(
        "mma.sync.aligned.m16n8k16.row.col.f32.bf16.bf16.f32 "
        "{%0,%1,%2,%3}, {%4,%5,%6,%7}, {%8,%9}, {%0,%1,%2,%3};"
        : "+f"(c[0]), "+f"(c[1]), "+f"(c[2]), "+f"(c[3])
        : "r"(a[0]), "r"(a[1]), "r"(a[2]), "r"(a[3]), "r"(b[0]), "r"(b[1]));
}

__device__ __forceinline__ void ld8(const float* __restrict__ p, float* d) {
    float4 v0 = *(const float4*)p;
    float4 v1 = *(const float4*)(p + 4);
    d[0] = v0.x; d[1] = v0.y; d[2] = v0.z; d[3] = v0.w;
    d[4] = v1.x; d[5] = v1.y; d[6] = v1.z; d[7] = v1.w;
}

// fp32[8] -> bf16 hi[8], lo[8].  hi = rn(x); lo = rn(x - hi).
__device__ __forceinline__ void split8(const float* f, __nv_bfloat16* hi, __nv_bfloat16* lo) {
    uint32_t hw[4], lw[4];
#pragma unroll
    for (int i = 0; i < 4; i++) {
        float a = f[2 * i], b = f[2 * i + 1];
        uint32_t h;
        asm("cvt.rn.bf16x2.f32 %0, %1, %2;" : "=r"(h) : "f"(b), "f"(a));
        float ha = __uint_as_float(h << 16);
        float hb = __uint_as_float(h & 0xFFFF0000u);
        uint32_t l;
        asm("cvt.rn.bf16x2.f32 %0, %1, %2;" : "=r"(l) : "f"(b - hb), "f"(a - ha));
        hw[i] = h; lw[i] = l;
    }
    *(uint4*)hi = make_uint4(hw[0], hw[1], hw[2], hw[3]);
    *(uint4*)lo = make_uint4(lw[0], lw[1], lw[2], lw[3]);
}

__device__ __forceinline__ void store_pair_split(__nv_bfloat16* hiP, __nv_bfloat16* loP,
                                                 float v0, float v1) {
    uint32_t h;
    asm("cvt.rn.bf16x2.f32 %0, %1, %2;" : "=r"(h) : "f"(v1), "f"(v0));
    float h0 = __uint_as_float(h << 16);
    float h1 = __uint_as_float(h & 0xFFFF0000u);
    uint32_t l;
    asm("cvt.rn.bf16x2.f32 %0, %1, %2;" : "=r"(l) : "f"(v1 - h1), "f"(v0 - h0));
    *(uint32_t*)hiP = h;
    *(uint32_t*)loP = l;
}

// ---------------------------------------------------------------------------
// MMA block: one K=32 smem stage -> 96 HMMA per warp (3-term bf16 split).
// XOR-swizzled layout: row r's 16B chunk c lives at position c ^ ((r>>1)&3).
// aRow/bRow are per-lane row byte offsets; xt0/xt1 the per-lane chunk offsets.
// ---------------------------------------------------------------------------
__device__ __forceinline__ void mma_block(uint32_t base, uint32_t aRow, uint32_t bRow,
                                          uint32_t xt0, uint32_t xt1,
                                          float acc[4][4][4]) {
    const uint32_t aHi = base;
    const uint32_t aLo = base + ARR_BYTES;
    const uint32_t bHi = base + 2 * ARR_BYTES;
    const uint32_t bLo = base + 3 * ARR_BYTES;
#pragma unroll
    for (int ks = 0; ks < 2; ks++) {
        const uint32_t xt = ks ? xt1 : xt0;
        uint32_t ah[4][4], al[4][4], bhf[4][2], blf[4][2];

#pragma unroll
        for (int mf = 0; mf < 4; mf++)
            ldsm4(ah[mf][0], ah[mf][1], ah[mf][2], ah[mf][3],
                  aHi + aRow + mf * (16 * ROWB) + xt);
#pragma unroll
        for (int p = 0; p < 2; p++) {
            uint32_t r0, r1, r2, r3;
            ldsm4(r0, r1, r2, r3, bHi + bRow + p * (16 * ROWB) + xt);
            bhf[2 * p][0] = r0; bhf[2 * p][1] = r2;
            bhf[2 * p + 1][0] = r1; bhf[2 * p + 1][1] = r3;
        }
#pragma unroll
        for (int mf = 0; mf < 4; mf++)
#pragma unroll
            for (int nf = 0; nf < 4; nf++)
                mma_bf16(acc[mf][nf], ah[mf], bhf[nf]);

#pragma unroll
        for (int p = 0; p < 2; p++) {
            uint32_t r0, r1, r2, r3;
            ldsm4(r0, r1, r2, r3, bLo + bRow + p * (16 * ROWB) + xt);
            blf[2 * p][0] = r0; blf[2 * p][1] = r2;
            blf[2 * p + 1][0] = r1; blf[2 * p + 1][1] = r3;
        }
#pragma unroll
        for (int mf = 0; mf < 4; mf++)
#pragma unroll
            for (int nf = 0; nf < 4; nf++)
                mma_bf16(acc[mf][nf], ah[mf], blf[nf]);

#pragma unroll
        for (int mf = 0; mf < 4; mf++)
            ldsm4(al[mf][0], al[mf][1], al[mf][2], al[mf][3],
                  aLo + aRow + mf * (16 * ROWB) + xt);
#pragma unroll
        for (int mf = 0; mf < 4; mf++)
#pragma unroll
            for (int nf = 0; nf < 4; nf++)
                mma_bf16(acc[mf][nf], al[mf], bhf[nf]);
    }
}

// ---------------------------------------------------------------------------
// Mainloop: acc += A[128,1024] * B[128,1024]^T, pre-split bf16 in gmem,
// 2-stage cp.async pipeline. R12 thread mapping (coalesced LDG) + XOR-swizzled
// smem (conflict-free STS AND ldmatrix).
// ---------------------------------------------------------------------------
__device__ __forceinline__ void mma_mainloop(const __nv_bfloat16* __restrict__ Ahi,
                                             const __nv_bfloat16* __restrict__ Alo,
                                             const __nv_bfloat16* __restrict__ Bhi,
                                             const __nv_bfloat16* __restrict__ Blo,
                                             float acc[4][4][4]) {
    extern __shared__ __align__(16) char sbuf[];
    const int tid = threadIdx.x;
    const int lane = tid & 31;
    const int wid = tid >> 5;
    const int wm = wid & 1;
    const int wn = wid >> 1;

#pragma unroll
    for (int i = 0; i < 4; i++)
#pragma unroll
        for (int j = 0; j < 4; j++)
#pragma unroll
            for (int k = 0; k < 4; k++) acc[i][j][k] = 0.f;

    const uint32_t sb = smem_u32(sbuf);
    const __nv_bfloat16* srcs[4] = {Ahi, Alo, Bhi, Blo};

    // copy assignment (R12): thread covers rows r0 and r0+64, chunk ch (16B)
    const int r0 = tid >> 2, ch = tid & 3;
    const int r1 = r0 + 64;
    const uint32_t xw = (uint32_t)((ch ^ ((r0 >> 1) & 3)) * 16);  // same for r1 (+64)
    const uint32_t s0 = (uint32_t)(r0 * ROWB) + xw;
    const uint32_t s1 = (uint32_t)(r1 * ROWB) + xw;
    const size_t o0 = (size_t)r0 * 1024 + ch * 8;
    const size_t o1 = (size_t)r1 * 1024 + ch * 8;

    auto copy_stage = [&](int slot, int k0) {
        uint32_t base = sb + slot * STAGE_BYTES;
#pragma unroll
        for (int a = 0; a < 4; a++) {
            cp16(base + a * ARR_BYTES + s0, srcs[a] + o0 + k0);
            cp16(base + a * ARR_BYTES + s1, srcs[a] + o1 + k0);
        }
    };

    copy_stage(0, 0);  CP_COMMIT();
    copy_stage(1, 32); CP_COMMIT();

    // ldmatrix per-lane addressing with swizzle
    const int row16 = lane & 15;
    const int xorb = (row16 >> 1) & 3;
    const uint32_t xt0 = (uint32_t)((((lane >> 4)    ) ^ xorb) * 16);  // ks=0
    const uint32_t xt1 = (uint32_t)(((2 + (lane >> 4)) ^ xorb) * 16);  // ks=1
    const uint32_t aRow = (uint32_t)((wm * 64 + row16) * ROWB);
    const uint32_t bRow = (uint32_t)((wn * 32 + row16) * ROWB);

    for (int ko = 0; ko < 32; ko++) {
        CP_WAIT1();            // group ko landed
        __syncthreads();       // all warps see stage ko
        mma_block(sb + (ko & 1) * STAGE_BYTES, aRow, bRow, xt0, xt1, acc);
        __syncthreads();       // all warps done reading slot ko&1
        if (ko + 2 < 32) copy_stage(ko & 1, (ko + 2) * 32);
        CP_COMMIT();           // keep group count exact
    }
}

// ---------------------------------------------------------------------------
// Pre-pass: split x and W into bf16 hi/lo (globals referenced from device code)
// ---------------------------------------------------------------------------
__global__ __launch_bounds__(256)
void conv_split_all_kernel(const float* __restrict__ x, const float* __restrict__ W) {
    size_t idx = (size_t)blockIdx.x * 256 + threadIdx.x;
    if (idx < (size_t)N8X) {
        float f[8];
        ld8(x + idx * 8, f);
        split8(f, g_xhi + idx * 8, g_xlo + idx * 8);
    } else if (idx < (size_t)(N8X + N8W)) {
        size_t j = idx - N8X;
        float f[8];
        ld8(W + j * 8, f);
        split8(f, g_Whi + j * 8, g_Wlo + j * 8);
    }
}

// ---------------------------------------------------------------------------
// Transpose + split: g_xT{hi,lo}[b][d][t] = split(x[b][t][d])
// ---------------------------------------------------------------------------
__global__ __launch_bounds__(256)
void transpose_split_kernel(const float* __restrict__ X) {
    __shared__ float tile[32][33];
    int b = blockIdx.z;
    int t0 = blockIdx.x * 32;
    int d0 = blockIdx.y * 32;
    const float* src = X + (size_t)b * S * D;
    int tx = threadIdx.x & 31, ty = threadIdx.x >> 5;
#pragma unroll
    for (int i = 0; i < 32; i += 8)
        tile[ty + i][tx] = src[(size_t)(t0 + ty + i) * D + d0 + tx];
    __syncthreads();

    int half = tx >> 4;        // 0: write hi, 1: write lo
    int k = tx & 15;           // t-pair index
#pragma unroll
    for (int i = 0; i < 32; i += 8) {
        int d = ty + i;
        float v0 = tile[2 * k][d], v1 = tile[2 * k + 1][d];
        uint32_t h;
        asm("cvt.rn.bf16x2.f32 %0, %1, %2;" : "=r"(h) : "f"(v1), "f"(v0));
        size_t off = (size_t)b * S * D + (size_t)(d0 + d) * 1024 + t0 + 2 * k;
        if (half == 0) {
            *(uint32_t*)&g_xThi[off] = h;
        } else {
            float h0 = __uint_as_float(h << 16);
            float h1 = __uint_as_float(h & 0xFFFF0000u);
            uint32_t l;
            asm("cvt.rn.bf16x2.f32 %0, %1, %2;" : "=r"(l) : "f"(v1 - h1), "f"(v0 - h0));
            *(uint32_t*)&g_xTlo[off] = l;
        }
    }
}

// ---------------------------------------------------------------------------
// GEMM1: xtran = x @ W^T + bias -> split bf16 hi/lo
// ---------------------------------------------------------------------------
__global__ __launch_bounds__(256, 2)
void gemm1_kernel(const float* __restrict__ bias) {
    const int m0 = blockIdx.y * 128;
    const int n0 = blockIdx.x * 128;

    float acc[4][4][4];
    mma_mainloop(g_xhi + (size_t)m0 * 1024, g_xlo + (size_t)m0 * 1024,
                 g_Whi + (size_t)n0 * 1024, g_Wlo + (size_t)n0 * 1024, acc);

    const int lane = threadIdx.x & 31, wid = threadIdx.x >> 5;
    const int wm = wid & 1, wn = wid >> 1;

#pragma unroll
    for (int mf = 0; mf < 4; mf++)
#pragma unroll
        for (int nf = 0; nf < 4; nf++) {
            int col = n0 + wn * 32 + nf * 8 + (lane & 3) * 2;
            float b0 = __ldg(&bias[col]), b1 = __ldg(&bias[col + 1]);
#pragma unroll
            for (int h = 0; h < 2; h++) {
                int row = m0 + wm * 64 + mf * 16 + (lane >> 2) + h * 8;
                size_t off = (size_t)row * 1024 + col;
                store_pair_split(&g_xthi[off], &g_xtlo[off],
                                 acc[mf][nf][h * 2 + 0] + b0,
                                 acc[mf][nf][h * 2 + 1] + b1);
            }
        }
}

// ---------------------------------------------------------------------------
// GEMM2: weights[b] = xtran[b] @ x[b]^T + decay/opinion/exp(tanh)/mask epilogue
// ---------------------------------------------------------------------------
__global__ __launch_bounds__(256, 2)
void gemm2_kernel(const float* __restrict__ go, const float* __restrict__ po,
                  const float* __restrict__ gprob) {
    const int b  = blockIdx.z;
    const int m0 = blockIdx.y * 128;
    const int n0 = blockIdx.x * 128;

    float acc[4][4][4];
    mma_mainloop(g_xthi + ((size_t)b * S + m0) * 1024, g_xtlo + ((size_t)b * S + m0) * 1024,
                 g_xhi  + ((size_t)b * S + n0) * 1024, g_xlo  + ((size_t)b * S + n0) * 1024, acc);

    const int lane = threadIdx.x & 31, wid = threadIdx.x >> 5;
    const int wm = wid & 1, wn = wid >> 1;
    const float gp = __ldg(gprob);

#pragma unroll
    for (int mf = 0; mf < 4; mf++) {
#pragma unroll
        for (int h = 0; h < 2; h++) {
            int s = m0 + wm * 64 + mf * 16 + (lane >> 2) + h * 8;
            const float* goP = go + ((size_t)b * S + s) * 5;
            const float* poP = po + ((size_t)b * S + s) * 5;
            float ow = gp * (__ldg(&goP[1]) + __ldg(&goP[2])) +
                       (1.f - gp) * (__ldg(&poP[3]) + __ldg(&poP[4]));
#pragma unroll
            for (int nf = 0; nf < 4; nf++) {
                int t0 = n0 + wn * 32 + nf * 8 + (lane & 3) * 2;
                float v[2];
#pragma unroll
                for (int j = 0; j < 2; j++) {
                    int t = t0 + j;
                    float w = acc[mf][nf][h * 2 + j] * ow;
                    float loc = fabsf((float)(s - t));
                    w = __fdividef(w, loc + EPS);
                    float e2 = __expf(2.f * w);
                    float th = 1.f - __fdividef(2.f, e2 + 1.f);
                    float r = __expf(th);
                    if (s == t) r = 0.f;
                    v[j] = r;
                }
                size_t off = ((size_t)b * S + s) * S + t0;
                store_pair_split(&g_whi[off], &g_wlo[off], v[0], v[1]);
            }
        }
    }
}

// ---------------------------------------------------------------------------
// Rowsum over weights rows (reads hi+lo)
// ---------------------------------------------------------------------------
__device__ __forceinline__ float sum_bf2(uint32_t u) {
    __nv_bfloat162 v = *reinterpret_cast<__nv_bfloat162*>(&u);
    float2 f = __bfloat1622float2(v);
    return f.x + f.y;
}

__global__ __launch_bounds__(256)
void rowsum_kernel() {
    const size_t row = blockIdx.x;
    const __nv_bfloat16* ph = g_whi + row * 1024;
    const __nv_bfloat16* pl = g_wlo + row * 1024;
    const int tid = threadIdx.x;

    uint2 uh = *(const uint2*)(ph + tid * 4);
    uint2 ul = *(const uint2*)(pl + tid * 4);
    float s = sum_bf2(uh.x) + sum_bf2(uh.y) + sum_bf2(ul.x) + sum_bf2(ul.y);

#pragma unroll
    for (int off = 16; off > 0; off >>= 1)
        s += __shfl_down_sync(0xFFFFFFFFu, s, off);

    __shared__ float warpsum[8];
    if ((tid & 31) == 0) warpsum[tid >> 5] = s;
    __syncthreads();
    if (tid < 8) {
        float t = warpsum[tid];
#pragma unroll
        for (int off = 4; off > 0; off >>= 1)
            t += __shfl_down_sync(0xFFu, t, off);
        if (tid == 0) g_rowsum[row] = t;
    }
}

// ---------------------------------------------------------------------------
// GEMM3: out[b] = (weights[b] / rowsum) @ x[b]   (B = xT hi/lo)
// ---------------------------------------------------------------------------
__global__ __launch_bounds__(256, 2)
void gemm3_kernel(float* __restrict__ out) {
    const int b  = blockIdx.z;
    const int m0 = blockIdx.y * 128;
    const int n0 = blockIdx.x * 128;

    float acc[4][4][4];
    mma_mainloop(g_whi  + ((size_t)b * S + m0) * 1024, g_wlo  + ((size_t)b * S + m0) * 1024,
                 g_xThi + ((size_t)b * D + n0) * 1024, g_xTlo + ((size_t)b * D + n0) * 1024, acc);

    const int lane = threadIdx.x & 31, wid = threadIdx.x >> 5;
    const int wm = wid & 1, wn = wid >> 1;
    float* Cb = out + (size_t)b * S * D;

#pragma unroll
    for (int mf = 0; mf < 4; mf++)
#pragma unroll
        for (int h = 0; h < 2; h++) {
            int s = m0 + wm * 64 + mf * 16 + (lane >> 2) + h * 8;
            float sc = 1.f / (g_rowsum[b * S + s] + EPS);
#pragma unroll
            for (int nf = 0; nf < 4; nf++) {
                int c0 = n0 + wn * 32 + nf * 8 + (lane & 3) * 2;
                float2 v = make_float2(acc[mf][nf][h * 2 + 0] * sc,
                                       acc[mf][nf][h * 2 + 1] * sc);
                *(float2*)&Cb[(size_t)s * 1024 + c0] = v;
            }
        }
}

// ---------------------------------------------------------------------------
extern "C" void kernel_launch(void* const* d_in, const int* in_sizes, int n_in,
                              void* d_out, int out_size)
{
    const float* x     = (const float*)d_in[0];  // [32,1024,1024]
    const float* W     = (const float*)d_in[1];  // [1024,1024]
    const float* bias  = (const float*)d_in[2];  // [1024]
    const float* go    = (const float*)d_in[3];  // [32,1024,5]
    const float* po    = (const float*)d_in[4];  // [32,1024,5]
    const float* gprob = (const float*)d_in[5];  // scalar
    float* out = (float*)d_out;

    cudaFuncSetAttribute(gemm1_kernel, cudaFuncAttributeMaxDynamicSharedMemorySize, SMEM_DYN);
    cudaFuncSetAttribute(gemm2_kernel, cudaFuncAttributeMaxDynamicSharedMemorySize, SMEM_DYN);
    cudaFuncSetAttribute(gemm3_kernel, cudaFuncAttributeMaxDynamicSharedMemorySize, SMEM_DYN);

    const int nConv = (N8X + N8W) / 256;   // 16896 blocks

    // Launch order chosen so ncu's captured launch (#4) is gemm2_kernel.
    conv_split_all_kernel<<<nConv, 256>>>(x, W);                        // 1
    transpose_split_kernel<<<dim3(32, 32, BATCH), 256>>>(x);            // 2
    gemm1_kernel<<<dim3(8, 256), 256, SMEM_DYN>>>(bias);                // 3
    gemm2_kernel<<<dim3(8, 8, BATCH), 256, SMEM_DYN>>>(go, po, gprob);  // 4  <- profiled
    rowsum_kernel<<<dim3(BATCH * S), 256>>>();                          // 5
    gemm3_kernel<<<dim3(8, 8, BATCH), 256, SMEM_DYN>>>(out);            // 6
}

// round 16
// speedup vs baseline: 1.5322x; 1.0101x over previous
#include <cuda_runtime.h>
#include <cuda_bf16.h>
#include <cstdint>
#include <math.h>

#define EPS 1e-5f

constexpr int BATCH = 32;
constexpr int S = 1024;
constexpr int D = 1024;

constexpr int ROWB = 64;                      // bytes per smem row (K=32 bf16, no pad)
constexpr int ARR_BYTES   = 128 * ROWB;       // 8192 B per operand array
constexpr int STAGE_BYTES = 4 * ARR_BYTES;    // 32768 B (Ahi,Alo,Bhi,Blo)
constexpr int NSTAGE = 3;
constexpr int SMEM_DYN = NSTAGE * STAGE_BYTES;  // 98304 B -> 2 CTAs/SM (192 <= 228 KB)

constexpr int N8X = BATCH * S * D / 8;   // 4194304
constexpr int N8W = D * D / 8;           // 131072

// ---------------------------------------------------------------------------
// Global scratch (allocation-free -> __device__ globals), bf16 hi/lo pairs.
// ONLY referenced from device code (R4/R5 bug: symbols passed as kernel args).
// ---------------------------------------------------------------------------
__device__ __align__(16) __nv_bfloat16 g_xhi[(size_t)BATCH * S * D];
__device__ __align__(16) __nv_bfloat16 g_xlo[(size_t)BATCH * S * D];
__device__ __align__(16) __nv_bfloat16 g_Whi[(size_t)D * D];
__device__ __align__(16) __nv_bfloat16 g_Wlo[(size_t)D * D];
__device__ __align__(16) __nv_bfloat16 g_xthi[(size_t)BATCH * S * D];   // xtran
__device__ __align__(16) __nv_bfloat16 g_xtlo[(size_t)BATCH * S * D];
__device__ __align__(16) __nv_bfloat16 g_whi[(size_t)BATCH * S * S];    // weights
__device__ __align__(16) __nv_bfloat16 g_wlo[(size_t)BATCH * S * S];
__device__ __align__(16) __nv_bfloat16 g_xThi[(size_t)BATCH * S * D];   // x^T
__device__ __align__(16) __nv_bfloat16 g_xTlo[(size_t)BATCH * S * D];
__device__ float g_rowsum[BATCH * S];

// ---------------------------------------------------------------------------
// helpers
// ---------------------------------------------------------------------------
__device__ __forceinline__ uint32_t smem_u32(const void* p) {
    uint32_t a;
    asm("{ .reg .u64 t; cvta.to.shared.u64 t, %1; cvt.u32.u64 %0, t; }" : "=r"(a) : "l"(p));
    return a;
}

__device__ __forceinline__ void cp16(uint32_t dst, const void* src) {
    asm volatile("cp.async.cg.shared.global [%0], [%1], 16;" :: "r"(dst), "l"(src) : "memory");
}
#define CP_COMMIT() asm volatile("cp.async.commit_group;" ::: "memory")
#define CP_WAIT1()  asm volatile("cp.async.wait_group 1;" ::: "memory")

__device__ __forceinline__ void ldsm4(uint32_t& r0, uint32_t& r1, uint32_t& r2, uint32_t& r3,
                                      uint32_t addr) {
    asm volatile("ldmatrix.sync.aligned.m8n8.x4.shared.b16 {%0,%1,%2,%3}, [%4];"
                 : "=r"(r0), "=r"(r1), "=r"(r2), "=r"(r3) : "r"(addr));
}

__device__ __forceinline__ void mma_bf16(float* c, const uint32_t* a, const uint32_t* b) {
    asm volatile(
        "mma.sync.aligned.m16n8k16.row.col.f32.bf16.bf16.f32 "
        "{%0,%1,%2,%3}, {%4,%5,%6,%7}, {%8,%9}, {%0,%1,%2,%3};"
        : "+f"(c[0]), "+f"(c[1]), "+f"(c[2]), "+f"(c[3])
        : "r"(a[0]), "r"(a[1]), "r"(a[2]), "r"(a[3]), "r"(b[0]), "r"(b[1]));
}

__device__ __forceinline__ void ld8(const float* __restrict__ p, float* d) {
    float4 v0 = *(const float4*)p;
    float4 v1 = *(const float4*)(p + 4);
    d[0] = v0.x; d[1] = v0.y; d[2] = v0.z; d[3] = v0.w;
    d[4] = v1.x; d[5] = v1.y; d[6] = v1.z; d[7] = v1.w;
}

// fp32[8] -> bf16 hi[8], lo[8].  hi = rn(x); lo = rn(x - hi).
__device__ __forceinline__ void split8(const float* f, __nv_bfloat16* hi, __nv_bfloat16* lo) {
    uint32_t hw[4], lw[4];
#pragma unroll
    for (int i = 0; i < 4; i++) {
        float a = f[2 * i], b = f[2 * i + 1];
        uint32_t h;
        asm("cvt.rn.bf16x2.f32 %0, %1, %2;" : "=r"(h) : "f"(b), "f"(a));
        float ha = __uint_as_float(h << 16);
        float hb = __uint_as_float(h & 0xFFFF0000u);
        uint32_t l;
        asm("cvt.rn.bf16x2.f32 %0, %1, %2;" : "=r"(l) : "f"(b - hb), "f"(a - ha));
        hw[i] = h; lw[i] = l;
    }
    *(uint4*)hi = make_uint4(hw[0], hw[1], hw[2], hw[3]);
    *(uint4*)lo = make_uint4(lw[0], lw[1], lw[2], lw[3]);
}

__device__ __forceinline__ void store_pair_split(__nv_bfloat16* hiP, __nv_bfloat16* loP,
                                                 float v0, float v1) {
    uint32_t h;
    asm("cvt.rn.bf16x2.f32 %0, %1, %2;" : "=r"(h) : "f"(v1), "f"(v0));
    float h0 = __uint_as_float(h << 16);
    float h1 = __uint_as_float(h & 0xFFFF0000u);
    uint32_t l;
    asm("cvt.rn.bf16x2.f32 %0, %1, %2;" : "=r"(l) : "f"(v1 - h1), "f"(v0 - h0));
    *(uint32_t*)hiP = h;
    *(uint32_t*)loP = l;
}

// ---------------------------------------------------------------------------
// MMA block: one K=32 smem stage -> 96 HMMA per warp (3-term bf16 split).
// XOR-swizzled layout: row r's 16B chunk c lives at position c ^ ((r>>1)&3).
// ---------------------------------------------------------------------------
__device__ __forceinline__ void mma_block(uint32_t base, uint32_t aRow, uint32_t bRow,
                                          uint32_t xt0, uint32_t xt1,
                                          float acc[4][4][4]) {
    const uint32_t aHi = base;
    const uint32_t aLo = base + ARR_BYTES;
    const uint32_t bHi = base + 2 * ARR_BYTES;
    const uint32_t bLo = base + 3 * ARR_BYTES;
#pragma unroll
    for (int ks = 0; ks < 2; ks++) {
        const uint32_t xt = ks ? xt1 : xt0;
        uint32_t ah[4][4], al[4][4], bhf[4][2], blf[4][2];

#pragma unroll
        for (int mf = 0; mf < 4; mf++)
            ldsm4(ah[mf][0], ah[mf][1], ah[mf][2], ah[mf][3],
                  aHi + aRow + mf * (16 * ROWB) + xt);
#pragma unroll
        for (int p = 0; p < 2; p++) {
            uint32_t r0, r1, r2, r3;
            ldsm4(r0, r1, r2, r3, bHi + bRow + p * (16 * ROWB) + xt);
            bhf[2 * p][0] = r0; bhf[2 * p][1] = r2;
            bhf[2 * p + 1][0] = r1; bhf[2 * p + 1][1] = r3;
        }
#pragma unroll
        for (int mf = 0; mf < 4; mf++)
#pragma unroll
            for (int nf = 0; nf < 4; nf++)
                mma_bf16(acc[mf][nf], ah[mf], bhf[nf]);

#pragma unroll
        for (int p = 0; p < 2; p++) {
            uint32_t r0, r1, r2, r3;
            ldsm4(r0, r1, r2, r3, bLo + bRow + p * (16 * ROWB) + xt);
            blf[2 * p][0] = r0; blf[2 * p][1] = r2;
            blf[2 * p + 1][0] = r1; blf[2 * p + 1][1] = r3;
        }
#pragma unroll
        for (int mf = 0; mf < 4; mf++)
#pragma unroll
            for (int nf = 0; nf < 4; nf++)
                mma_bf16(acc[mf][nf], ah[mf], blf[nf]);

#pragma unroll
        for (int mf = 0; mf < 4; mf++)
            ldsm4(al[mf][0], al[mf][1], al[mf][2], al[mf][3],
                  aLo + aRow + mf * (16 * ROWB) + xt);
#pragma unroll
        for (int mf = 0; mf < 4; mf++)
#pragma unroll
            for (int nf = 0; nf < 4; nf++)
                mma_bf16(acc[mf][nf], al[mf], bhf[nf]);
    }
}

// ---------------------------------------------------------------------------
// Mainloop: acc += A[128,1024] * B[128,1024]^T, pre-split bf16 in gmem,
// 3-stage cp.async pipeline, ONE barrier per iteration (slot written at iter
// ko is (ko+2)%3, last read at iter ko-1 -> ordered by the sync at iter ko).
// ---------------------------------------------------------------------------
__device__ __forceinline__ void mma_mainloop(const __nv_bfloat16* __restrict__ Ahi,
                                             const __nv_bfloat16* __restrict__ Alo,
                                             const __nv_bfloat16* __restrict__ Bhi,
                                             const __nv_bfloat16* __restrict__ Blo,
                                             float acc[4][4][4]) {
    extern __shared__ __align__(16) char sbuf[];
    const int tid = threadIdx.x;
    const int lane = tid & 31;
    const int wid = tid >> 5;
    const int wm = wid & 1;
    const int wn = wid >> 1;

#pragma unroll
    for (int i = 0; i < 4; i++)
#pragma unroll
        for (int j = 0; j < 4; j++)
#pragma unroll
            for (int k = 0; k < 4; k++) acc[i][j][k] = 0.f;

    const uint32_t sb = smem_u32(sbuf);
    const __nv_bfloat16* srcs[4] = {Ahi, Alo, Bhi, Blo};

    // copy assignment (R12/R15): thread covers rows r0 and r0+64, chunk ch (16B)
    const int r0 = tid >> 2, ch = tid & 3;
    const int r1 = r0 + 64;
    const uint32_t xw = (uint32_t)((ch ^ ((r0 >> 1) & 3)) * 16);  // same for r1 (+64)
    const uint32_t s0 = (uint32_t)(r0 * ROWB) + xw;
    const uint32_t s1 = (uint32_t)(r1 * ROWB) + xw;
    const size_t o0 = (size_t)r0 * 1024 + ch * 8;
    const size_t o1 = (size_t)r1 * 1024 + ch * 8;

    auto copy_stage = [&](int slot, int k0) {
        uint32_t base = sb + slot * STAGE_BYTES;
#pragma unroll
        for (int a = 0; a < 4; a++) {
            cp16(base + a * ARR_BYTES + s0, srcs[a] + o0 + k0);
            cp16(base + a * ARR_BYTES + s1, srcs[a] + o1 + k0);
        }
    };

    copy_stage(0, 0);  CP_COMMIT();
    copy_stage(1, 32); CP_COMMIT();

    // ldmatrix per-lane addressing with swizzle
    const int row16 = lane & 15;
    const int xorb = (row16 >> 1) & 3;
    const uint32_t xt0 = (uint32_t)((((lane >> 4)    ) ^ xorb) * 16);  // ks=0
    const uint32_t xt1 = (uint32_t)(((2 + (lane >> 4)) ^ xorb) * 16);  // ks=1
    const uint32_t aRow = (uint32_t)((wm * 64 + row16) * ROWB);
    const uint32_t bRow = (uint32_t)((wn * 32 + row16) * ROWB);

    int slot = 0;          // slot of stage ko
    int wslot = 2;         // slot to write stage ko+2 into
    for (int ko = 0; ko < 32; ko++) {
        CP_WAIT1();            // stage ko landed
        __syncthreads();       // all warps see it; all warps done with slot wslot (read at ko-1)
        if (ko + 2 < 32) copy_stage(wslot, (ko + 2) * 32);
        CP_COMMIT();           // keep group count exact
        mma_block(sb + slot * STAGE_BYTES, aRow, bRow, xt0, xt1, acc);
        slot = (slot == 2) ? 0 : slot + 1;
        wslot = (wslot == 2) ? 0 : wslot + 1;
    }
}

// ---------------------------------------------------------------------------
// Pre-pass: split x and W into bf16 hi/lo (globals referenced from device code)
// ---------------------------------------------------------------------------
__global__ __launch_bounds__(256)
void conv_split_all_kernel(const float* __restrict__ x, const float* __restrict__ W) {
    size_t idx = (size_t)blockIdx.x * 256 + threadIdx.x;
    if (idx < (size_t)N8X) {
        float f[8];
        ld8(x + idx * 8, f);
        split8(f, g_xhi + idx * 8, g_xlo + idx * 8);
    } else if (idx < (size_t)(N8X + N8W)) {
        size_t j = idx - N8X;
        float f[8];
        ld8(W + j * 8, f);
        split8(f, g_Whi + j * 8, g_Wlo + j * 8);
    }
}

// ---------------------------------------------------------------------------
// Transpose + split: g_xT{hi,lo}[b][d][t] = split(x[b][t][d])
// ---------------------------------------------------------------------------
__global__ __launch_bounds__(256)
void transpose_split_kernel(const float* __restrict__ X) {
    __shared__ float tile[32][33];
    int b = blockIdx.z;
    int t0 = blockIdx.x * 32;
    int d0 = blockIdx.y * 32;
    const float* src = X + (size_t)b * S * D;
    int tx = threadIdx.x & 31, ty = threadIdx.x >> 5;
#pragma unroll
    for (int i = 0; i < 32; i += 8)
        tile[ty + i][tx] = src[(size_t)(t0 + ty + i) * D + d0 + tx];
    __syncthreads();

    int half = tx >> 4;        // 0: write hi, 1: write lo
    int k = tx & 15;           // t-pair index
#pragma unroll
    for (int i = 0; i < 32; i += 8) {
        int d = ty + i;
        float v0 = tile[2 * k][d], v1 = tile[2 * k + 1][d];
        uint32_t h;
        asm("cvt.rn.bf16x2.f32 %0, %1, %2;" : "=r"(h) : "f"(v1), "f"(v0));
        size_t off = (size_t)b * S * D + (size_t)(d0 + d) * 1024 + t0 + 2 * k;
        if (half == 0) {
            *(uint32_t*)&g_xThi[off] = h;
        } else {
            float h0 = __uint_as_float(h << 16);
            float h1 = __uint_as_float(h & 0xFFFF0000u);
            uint32_t l;
            asm("cvt.rn.bf16x2.f32 %0, %1, %2;" : "=r"(l) : "f"(v1 - h1), "f"(v0 - h0));
            *(uint32_t*)&g_xTlo[off] = l;
        }
    }
}

// ---------------------------------------------------------------------------
// GEMM1: xtran = x @ W^T + bias -> split bf16 hi/lo
// ---------------------------------------------------------------------------
__global__ __launch_bounds__(256, 2)
void gemm1_kernel(const float* __restrict__ bias) {
    const int m0 = blockIdx.y * 128;
    const int n0 = blockIdx.x * 128;

    float acc[4][4][4];
    mma_mainloop(g_xhi + (size_t)m0 * 1024, g_xlo + (size_t)m0 * 1024,
                 g_Whi + (size_t)n0 * 1024, g_Wlo + (size_t)n0 * 1024, acc);

    const int lane = threadIdx.x & 31, wid = threadIdx.x >> 5;
    const int wm = wid & 1, wn = wid >> 1;

#pragma unroll
    for (int mf = 0; mf < 4; mf++)
#pragma unroll
        for (int nf = 0; nf < 4; nf++) {
            int col = n0 + wn * 32 + nf * 8 + (lane & 3) * 2;
            float b0 = __ldg(&bias[col]), b1 = __ldg(&bias[col + 1]);
#pragma unroll
            for (int h = 0; h < 2; h++) {
                int row = m0 + wm * 64 + mf * 16 + (lane >> 2) + h * 8;
                size_t off = (size_t)row * 1024 + col;
                store_pair_split(&g_xthi[off], &g_xtlo[off],
                                 acc[mf][nf][h * 2 + 0] + b0,
                                 acc[mf][nf][h * 2 + 1] + b1);
            }
        }
}

// ---------------------------------------------------------------------------
// GEMM2: weights[b] = xtran[b] @ x[b]^T + decay/opinion/exp(tanh)/mask epilogue
// ---------------------------------------------------------------------------
__global__ __launch_bounds__(256, 2)
void gemm2_kernel(const float* __restrict__ go, const float* __restrict__ po,
                  const float* __restrict__ gprob) {
    const int b  = blockIdx.z;
    const int m0 = blockIdx.y * 128;
    const int n0 = blockIdx.x * 128;

    float acc[4][4][4];
    mma_mainloop(g_xthi + ((size_t)b * S + m0) * 1024, g_xtlo + ((size_t)b * S + m0) * 1024,
                 g_xhi  + ((size_t)b * S + n0) * 1024, g_xlo  + ((size_t)b * S + n0) * 1024, acc);

    const int lane = threadIdx.x & 31, wid = threadIdx.x >> 5;
    const int wm = wid & 1, wn = wid >> 1;
    const float gp = __ldg(gprob);

#pragma unroll
    for (int mf = 0; mf < 4; mf++) {
#pragma unroll
        for (int h = 0; h < 2; h++) {
            int s = m0 + wm * 64 + mf * 16 + (lane >> 2) + h * 8;
            const float* goP = go + ((size_t)b * S + s) * 5;
            const float* poP = po + ((size_t)b * S + s) * 5;
            float ow = gp * (__ldg(&goP[1]) + __ldg(&goP[2])) +
                       (1.f - gp) * (__ldg(&poP[3]) + __ldg(&poP[4]));
#pragma unroll
            for (int nf = 0; nf < 4; nf++) {
                int t0 = n0 + wn * 32 + nf * 8 + (lane & 3) * 2;
                float v[2];
#pragma unroll
                for (int j = 0; j < 2; j++) {
                    int t = t0 + j;
                    float w = acc[mf][nf][h * 2 + j] * ow;
                    float loc = fabsf((float)(s - t));
                    w = __fdividef(w, loc + EPS);
                    float e2 = __expf(2.f * w);
                    float th = 1.f - __fdividef(2.f, e2 + 1.f);
                    float r = __expf(th);
                    if (s == t) r = 0.f;
                    v[j] = r;
                }
                size_t off = ((size_t)b * S + s) * S + t0;
                store_pair_split(&g_whi[off], &g_wlo[off], v[0], v[1]);
            }
        }
    }
}

// ---------------------------------------------------------------------------
// Rowsum over weights rows (reads hi+lo)
// ---------------------------------------------------------------------------
__device__ __forceinline__ float sum_bf2(uint32_t u) {
    __nv_bfloat162 v = *reinterpret_cast<__nv_bfloat162*>(&u);
    float2 f = __bfloat1622float2(v);
    return f.x + f.y;
}

__global__ __launch_bounds__(256)
void rowsum_kernel() {
    const size_t row = blockIdx.x;
    const __nv_bfloat16* ph = g_whi + row * 1024;
    const __nv_bfloat16* pl = g_wlo + row * 1024;
    const int tid = threadIdx.x;

    uint2 uh = *(const uint2*)(ph + tid * 4);
    uint2 ul = *(const uint2*)(pl + tid * 4);
    float s = sum_bf2(uh.x) + sum_bf2(uh.y) + sum_bf2(ul.x) + sum_bf2(ul.y);

#pragma unroll
    for (int off = 16; off > 0; off >>= 1)
        s += __shfl_down_sync(0xFFFFFFFFu, s, off);

    __shared__ float warpsum[8];
    if ((tid & 31) == 0) warpsum[tid >> 5] = s;
    __syncthreads();
    if (tid < 8) {
        float t = warpsum[tid];
#pragma unroll
        for (int off = 4; off > 0; off >>= 1)
            t += __shfl_down_sync(0xFFu, t, off);
        if (tid == 0) g_rowsum[row] = t;
    }
}

// ---------------------------------------------------------------------------
// GEMM3: out[b] = (weights[b] / rowsum) @ x[b]   (B = xT hi/lo)
// ---------------------------------------------------------------------------
__global__ __launch_bounds__(256, 2)
void gemm3_kernel(float* __restrict__ out) {
    const int b  = blockIdx.z;
    const int m0 = blockIdx.y * 128;
    const int n0 = blockIdx.x * 128;

    float acc[4][4][4];
    mma_mainloop(g_whi  + ((size_t)b * S + m0) * 1024, g_wlo  + ((size_t)b * S + m0) * 1024,
                 g_xThi + ((size_t)b * D + n0) * 1024, g_xTlo + ((size_t)b * D + n0) * 1024, acc);

    const int lane = threadIdx.x & 31, wid = threadIdx.x >> 5;
    const int wm = wid & 1, wn = wid >> 1;
    float* Cb = out + (size_t)b * S * D;

#pragma unroll
    for (int mf = 0; mf < 4; mf++)
#pragma unroll
        for (int h = 0; h < 2; h++) {
            int s = m0 + wm * 64 + mf * 16 + (lane >> 2) + h * 8;
            float sc = 1.f / (g_rowsum[b * S + s] + EPS);
#pragma unroll
            for (int nf = 0; nf < 4; nf++) {
                int c0 = n0 + wn * 32 + nf * 8 + (lane & 3) * 2;
                float2 v = make_float2(acc[mf][nf][h * 2 + 0] * sc,
                                       acc[mf][nf][h * 2 + 1] * sc);
                *(float2*)&Cb[(size_t)s * 1024 + c0] = v;
            }
        }
}

// ---------------------------------------------------------------------------
extern "C" void kernel_launch(void* const* d_in, const int* in_sizes, int n_in,
                              void* d_out, int out_size)
{
    const float* x     = (const float*)d_in[0];  // [32,1024,1024]
    const float* W     = (const float*)d_in[1];  // [1024,1024]
    const float* bias  = (const float*)d_in[2];  // [1024]
    const float* go    = (const float*)d_in[3];  // [32,1024,5]
    const float* po    = (const float*)d_in[4];  // [32,1024,5]
    const float* gprob = (const float*)d_in[5];  // scalar
    float* out = (float*)d_out;

    cudaFuncSetAttribute(gemm1_kernel, cudaFuncAttributeMaxDynamicSharedMemorySize, SMEM_DYN);
    cudaFuncSetAttribute(gemm2_kernel, cudaFuncAttributeMaxDynamicSharedMemorySize, SMEM_DYN);
    cudaFuncSetAttribute(gemm3_kernel, cudaFuncAttributeMaxDynamicSharedMemorySize, SMEM_DYN);

    const int nConv = (N8X + N8W) / 256;   // 16896 blocks

    // Launch order chosen so ncu's captured launch (#4) is gemm2_kernel.
    conv_split_all_kernel<<<nConv, 256>>>(x, W);                        // 1
    transpose_split_kernel<<<dim3(32, 32, BATCH), 256>>>(x);            // 2
    gemm1_kernel<<<dim3(8, 256), 256, SMEM_DYN>>>(bias);                // 3
    gemm2_kernel<<<dim3(8, 8, BATCH), 256, SMEM_DYN>>>(go, po, gprob);  // 4  <- profiled
    rowsum_kernel<<<dim3(BATCH * S), 256>>>();                          // 5
    gemm3_kernel<<<dim3(8, 8, BATCH), 256, SMEM_DYN>>>(out);            // 6
}

// round 17
// speedup vs baseline: 1.5752x; 1.0281x over previous
#include <cuda_runtime.h>
#include <cuda_bf16.h>
#include <cstdint>
#include <math.h>

#define EPS 1e-5f

constexpr int BATCH = 32;
constexpr int S = 1024;
constexpr int D = 1024;

constexpr int ROWB = 64;                      // bytes per smem row (K=32 bf16, no pad)
constexpr int ARR_BYTES   = 128 * ROWB;       // 8192 B per operand array
constexpr int STAGE_BYTES = 4 * ARR_BYTES;    // 32768 B (Ahi,Alo,Bhi,Blo)
constexpr int NSTAGE = 3;
constexpr int SMEM_DYN = NSTAGE * STAGE_BYTES;  // 98304 B -> 2 CTAs/SM

constexpr int N8W = D * D / 8;           // 131072

// ---------------------------------------------------------------------------
// Global scratch (allocation-free -> __device__ globals), bf16 hi/lo pairs.
// ONLY referenced from device code.
// ---------------------------------------------------------------------------
__device__ __align__(16) __nv_bfloat16 g_xhi[(size_t)BATCH * S * D];
__device__ __align__(16) __nv_bfloat16 g_xlo[(size_t)BATCH * S * D];
__device__ __align__(16) __nv_bfloat16 g_Whi[(size_t)D * D];
__device__ __align__(16) __nv_bfloat16 g_Wlo[(size_t)D * D];
__device__ __align__(16) __nv_bfloat16 g_xthi[(size_t)BATCH * S * D];   // xtran
__device__ __align__(16) __nv_bfloat16 g_xtlo[(size_t)BATCH * S * D];
__device__ __align__(16) __nv_bfloat16 g_whi[(size_t)BATCH * S * S];    // weights
__device__ __align__(16) __nv_bfloat16 g_wlo[(size_t)BATCH * S * S];
__device__ __align__(16) __nv_bfloat16 g_xThi[(size_t)BATCH * S * D];   // x^T
__device__ __align__(16) __nv_bfloat16 g_xTlo[(size_t)BATCH * S * D];
__device__ float g_rowsum_part[(size_t)BATCH * S * 8];
__device__ float g_rowsum[BATCH * S];

// ---------------------------------------------------------------------------
// helpers
// ---------------------------------------------------------------------------
__device__ __forceinline__ uint32_t smem_u32(const void* p) {
    uint32_t a;
    asm("{ .reg .u64 t; cvta.to.shared.u64 t, %1; cvt.u32.u64 %0, t; }" : "=r"(a) : "l"(p));
    return a;
}

__device__ __forceinline__ void cp16(uint32_t dst, const void* src) {
    asm volatile("cp.async.cg.shared.global [%0], [%1], 16;" :: "r"(dst), "l"(src) : "memory");
}
#define CP_COMMIT() asm volatile("cp.async.commit_group;" ::: "memory")
#define CP_WAIT1()  asm volatile("cp.async.wait_group 1;" ::: "memory")

__device__ __forceinline__ void ldsm4(uint32_t& r0, uint32_t& r1, uint32_t& r2, uint32_t& r3,
                                      uint32_t addr) {
    asm volatile("ldmatrix.sync.aligned.m8n8.x4.shared.b16 {%0,%1,%2,%3}, [%4];"
                 : "=r"(r0), "=r"(r1), "=r"(r2), "=r"(r3) : "r"(addr));
}

__device__ __forceinline__ void mma_bf16(float* c, const uint32_t* a, const uint32_t* b) {
    asm volatile(
        "mma.sync.aligned.m16n8k16.row.col.f32.bf16.bf16.f32 "
        "{%0,%1,%2,%3}, {%4,%5,%6,%7}, {%8,%9}, {%0,%1,%2,%3};"
        : "+f"(c[0]), "+f"(c[1]), "+f"(c[2]), "+f"(c[3])
        : "r"(a[0]), "r"(a[1]), "r"(a[2]), "r"(a[3]), "r"(b[0]), "r"(b[1]));
}

__device__ __forceinline__ void ld8(const float* __restrict__ p, float* d) {
    float4 v0 = *(const float4*)p;
    float4 v1 = *(const float4*)(p + 4);
    d[0] = v0.x; d[1] = v0.y; d[2] = v0.z; d[3] = v0.w;
    d[4] = v1.x; d[5] = v1.y; d[6] = v1.z; d[7] = v1.w;
}

// fp32[8] -> bf16 hi[8], lo[8].  hi = rn(x); lo = rn(x - hi).
__device__ __forceinline__ void split8(const float* f, __nv_bfloat16* hi, __nv_bfloat16* lo) {
    uint32_t hw[4], lw[4];
#pragma unroll
    for (int i = 0; i < 4; i++) {
        float a = f[2 * i], b = f[2 * i + 1];
        uint32_t h;
        asm("cvt.rn.bf16x2.f32 %0, %1, %2;" : "=r"(h) : "f"(b), "f"(a));
        float ha = __uint_as_float(h << 16);
        float hb = __uint_as_float(h & 0xFFFF0000u);
        uint32_t l;
        asm("cvt.rn.bf16x2.f32 %0, %1, %2;" : "=r"(l) : "f"(b - hb), "f"(a - ha));
        hw[i] = h; lw[i] = l;
    }
    *(uint4*)hi = make_uint4(hw[0], hw[1], hw[2], hw[3]);
    *(uint4*)lo = make_uint4(lw[0], lw[1], lw[2], lw[3]);
}

__device__ __forceinline__ void store_pair_split(__nv_bfloat16* hiP, __nv_bfloat16* loP,
                                                 float v0, float v1) {
    uint32_t h;
    asm("cvt.rn.bf16x2.f32 %0, %1, %2;" : "=r"(h) : "f"(v1), "f"(v0));
    float h0 = __uint_as_float(h << 16);
    float h1 = __uint_as_float(h & 0xFFFF0000u);
    uint32_t l;
    asm("cvt.rn.bf16x2.f32 %0, %1, %2;" : "=r"(l) : "f"(v1 - h1), "f"(v0 - h0));
    *(uint32_t*)hiP = h;
    *(uint32_t*)loP = l;
}

// ---------------------------------------------------------------------------
// MMA block: one K=32 smem stage -> 96 HMMA per warp (3-term bf16 split).
// XOR-swizzled layout: row r's 16B chunk c lives at position c ^ ((r>>1)&3).
// ---------------------------------------------------------------------------
__device__ __forceinline__ void mma_block(uint32_t base, uint32_t aRow, uint32_t bRow,
                                          uint32_t xt0, uint32_t xt1,
                                          float acc[4][4][4]) {
    const uint32_t aHi = base;
    const uint32_t aLo = base + ARR_BYTES;
    const uint32_t bHi = base + 2 * ARR_BYTES;
    const uint32_t bLo = base + 3 * ARR_BYTES;
#pragma unroll
    for (int ks = 0; ks < 2; ks++) {
        const uint32_t xt = ks ? xt1 : xt0;
        uint32_t ah[4][4], al[4][4], bhf[4][2], blf[4][2];

#pragma unroll
        for (int mf = 0; mf < 4; mf++)
            ldsm4(ah[mf][0], ah[mf][1], ah[mf][2], ah[mf][3],
                  aHi + aRow + mf * (16 * ROWB) + xt);
#pragma unroll
        for (int p = 0; p < 2; p++) {
            uint32_t r0, r1, r2, r3;
            ldsm4(r0, r1, r2, r3, bHi + bRow + p * (16 * ROWB) + xt);
            bhf[2 * p][0] = r0; bhf[2 * p][1] = r2;
            bhf[2 * p + 1][0] = r1; bhf[2 * p + 1][1] = r3;
        }
#pragma unroll
        for (int mf = 0; mf < 4; mf++)
#pragma unroll
            for (int nf = 0; nf < 4; nf++)
                mma_bf16(acc[mf][nf], ah[mf], bhf[nf]);

#pragma unroll
        for (int p = 0; p < 2; p++) {
            uint32_t r0, r1, r2, r3;
            ldsm4(r0, r1, r2, r3, bLo + bRow + p * (16 * ROWB) + xt);
            blf[2 * p][0] = r0; blf[2 * p][1] = r2;
            blf[2 * p + 1][0] = r1; blf[2 * p + 1][1] = r3;
        }
#pragma unroll
        for (int mf = 0; mf < 4; mf++)
#pragma unroll
            for (int nf = 0; nf < 4; nf++)
                mma_bf16(acc[mf][nf], ah[mf], blf[nf]);

#pragma unroll
        for (int mf = 0; mf < 4; mf++)
            ldsm4(al[mf][0], al[mf][1], al[mf][2], al[mf][3],
                  aLo + aRow + mf * (16 * ROWB) + xt);
#pragma unroll
        for (int mf = 0; mf < 4; mf++)
#pragma unroll
            for (int nf = 0; nf < 4; nf++)
                mma_bf16(acc[mf][nf], al[mf], bhf[nf]);
    }
}

// ---------------------------------------------------------------------------
// Mainloop (identical to R16): 3-stage cp.async pipeline, one barrier/iter.
// ---------------------------------------------------------------------------
__device__ __forceinline__ void mma_mainloop(const __nv_bfloat16* __restrict__ Ahi,
                                             const __nv_bfloat16* __restrict__ Alo,
                                             const __nv_bfloat16* __restrict__ Bhi,
                                             const __nv_bfloat16* __restrict__ Blo,
                                             float acc[4][4][4]) {
    extern __shared__ __align__(16) char sbuf[];
    const int tid = threadIdx.x;
    const int lane = tid & 31;
    const int wid = tid >> 5;
    const int wm = wid & 1;
    const int wn = wid >> 1;

#pragma unroll
    for (int i = 0; i < 4; i++)
#pragma unroll
        for (int j = 0; j < 4; j++)
#pragma unroll
            for (int k = 0; k < 4; k++) acc[i][j][k] = 0.f;

    const uint32_t sb = smem_u32(sbuf);
    const __nv_bfloat16* srcs[4] = {Ahi, Alo, Bhi, Blo};

    const int r0 = tid >> 2, ch = tid & 3;
    const int r1 = r0 + 64;
    const uint32_t xw = (uint32_t)((ch ^ ((r0 >> 1) & 3)) * 16);
    const uint32_t s0 = (uint32_t)(r0 * ROWB) + xw;
    const uint32_t s1 = (uint32_t)(r1 * ROWB) + xw;
    const size_t o0 = (size_t)r0 * 1024 + ch * 8;
    const size_t o1 = (size_t)r1 * 1024 + ch * 8;

    auto copy_stage = [&](int slot, int k0) {
        uint32_t base = sb + slot * STAGE_BYTES;
#pragma unroll
        for (int a = 0; a < 4; a++) {
            cp16(base + a * ARR_BYTES + s0, srcs[a] + o0 + k0);
            cp16(base + a * ARR_BYTES + s1, srcs[a] + o1 + k0);
        }
    };

    copy_stage(0, 0);  CP_COMMIT();
    copy_stage(1, 32); CP_COMMIT();

    const int row16 = lane & 15;
    const int xorb = (row16 >> 1) & 3;
    const uint32_t xt0 = (uint32_t)((((lane >> 4)    ) ^ xorb) * 16);
    const uint32_t xt1 = (uint32_t)(((2 + (lane >> 4)) ^ xorb) * 16);
    const uint32_t aRow = (uint32_t)((wm * 64 + row16) * ROWB);
    const uint32_t bRow = (uint32_t)((wn * 32 + row16) * ROWB);

    int slot = 0;
    int wslot = 2;
    for (int ko = 0; ko < 32; ko++) {
        CP_WAIT1();
        __syncthreads();
        if (ko + 2 < 32) copy_stage(wslot, (ko + 2) * 32);
        CP_COMMIT();
        mma_block(sb + slot * STAGE_BYTES, aRow, bRow, xt0, xt1, acc);
        slot = (slot == 2) ? 0 : slot + 1;
        wslot = (wslot == 2) ? 0 : wslot + 1;
    }
}

// ---------------------------------------------------------------------------
// Combined prologue for x: one read of x produces row-major split (xhi/xlo)
// AND transposed split (xThi/xTlo).
// ---------------------------------------------------------------------------
__global__ __launch_bounds__(256)
void prep_x_kernel(const float* __restrict__ X) {
    __shared__ float tile[32][33];
    int b = blockIdx.z;
    int t0 = blockIdx.x * 32;
    int d0 = blockIdx.y * 32;
    const float* src = X + (size_t)b * S * D;
    int tx = threadIdx.x & 31, ty = threadIdx.x >> 5;

#pragma unroll
    for (int i = 0; i < 32; i += 8) {
        size_t off = (size_t)b * S * D + (size_t)(t0 + ty + i) * D + d0 + tx;
        float v = src[(size_t)(t0 + ty + i) * D + d0 + tx];
        tile[ty + i][tx] = v;
        // row-major split (2B stores, fully coalesced per warp)
        __nv_bfloat16 h = __float2bfloat16_rn(v);
        g_xhi[off] = h;
        g_xlo[off] = __float2bfloat16_rn(v - __bfloat162float(h));
    }
    __syncthreads();

    int half = tx >> 4;        // 0: write hi, 1: write lo
    int k = tx & 15;           // t-pair index
#pragma unroll
    for (int i = 0; i < 32; i += 8) {
        int d = ty + i;
        float v0 = tile[2 * k][d], v1 = tile[2 * k + 1][d];
        uint32_t h;
        asm("cvt.rn.bf16x2.f32 %0, %1, %2;" : "=r"(h) : "f"(v1), "f"(v0));
        size_t off = (size_t)b * S * D + (size_t)(d0 + d) * 1024 + t0 + 2 * k;
        if (half == 0) {
            *(uint32_t*)&g_xThi[off] = h;
        } else {
            float h0 = __uint_as_float(h << 16);
            float h1 = __uint_as_float(h & 0xFFFF0000u);
            uint32_t l;
            asm("cvt.rn.bf16x2.f32 %0, %1, %2;" : "=r"(l) : "f"(v1 - h1), "f"(v0 - h0));
            *(uint32_t*)&g_xTlo[off] = l;
        }
    }
}

// ---------------------------------------------------------------------------
// W split (small)
// ---------------------------------------------------------------------------
__global__ __launch_bounds__(256)
void conv_W_kernel(const float* __restrict__ W) {
    size_t idx = (size_t)blockIdx.x * 256 + threadIdx.x;
    if (idx < (size_t)N8W) {
        float f[8];
        ld8(W + idx * 8, f);
        split8(f, g_Whi + idx * 8, g_Wlo + idx * 8);
    }
}

// ---------------------------------------------------------------------------
// GEMM1: xtran = x @ W^T + bias -> split bf16 hi/lo
// ---------------------------------------------------------------------------
__global__ __launch_bounds__(256, 2)
void gemm1_kernel(const float* __restrict__ bias) {
    const int m0 = blockIdx.y * 128;
    const int n0 = blockIdx.x * 128;

    float acc[4][4][4];
    mma_mainloop(g_xhi + (size_t)m0 * 1024, g_xlo + (size_t)m0 * 1024,
                 g_Whi + (size_t)n0 * 1024, g_Wlo + (size_t)n0 * 1024, acc);

    const int lane = threadIdx.x & 31, wid = threadIdx.x >> 5;
    const int wm = wid & 1, wn = wid >> 1;

#pragma unroll
    for (int mf = 0; mf < 4; mf++)
#pragma unroll
        for (int nf = 0; nf < 4; nf++) {
            int col = n0 + wn * 32 + nf * 8 + (lane & 3) * 2;
            float b0 = __ldg(&bias[col]), b1 = __ldg(&bias[col + 1]);
#pragma unroll
            for (int h = 0; h < 2; h++) {
                int row = m0 + wm * 64 + mf * 16 + (lane >> 2) + h * 8;
                size_t off = (size_t)row * 1024 + col;
                store_pair_split(&g_xthi[off], &g_xtlo[off],
                                 acc[mf][nf][h * 2 + 0] + b0,
                                 acc[mf][nf][h * 2 + 1] + b1);
            }
        }
}

// ---------------------------------------------------------------------------
// GEMM2: weights[b] = xtran[b] @ x[b]^T + epilogue + fused rowsum partials
// ---------------------------------------------------------------------------
__global__ __launch_bounds__(256, 2)
void gemm2_kernel(const float* __restrict__ go, const float* __restrict__ po,
                  const float* __restrict__ gprob) {
    const int b  = blockIdx.z;
    const int m0 = blockIdx.y * 128;
    const int n0 = blockIdx.x * 128;

    float acc[4][4][4];
    mma_mainloop(g_xthi + ((size_t)b * S + m0) * 1024, g_xtlo + ((size_t)b * S + m0) * 1024,
                 g_xhi  + ((size_t)b * S + n0) * 1024, g_xlo  + ((size_t)b * S + n0) * 1024, acc);

    __shared__ float sp[128][4];

    const int lane = threadIdx.x & 31, wid = threadIdx.x >> 5;
    const int wm = wid & 1, wn = wid >> 1;
    const float gp = __ldg(gprob);

#pragma unroll
    for (int mf = 0; mf < 4; mf++) {
#pragma unroll
        for (int h = 0; h < 2; h++) {
            int rl = wm * 64 + mf * 16 + (lane >> 2) + h * 8;
            int s = m0 + rl;
            const float* goP = go + ((size_t)b * S + s) * 5;
            const float* poP = po + ((size_t)b * S + s) * 5;
            float ow = gp * (__ldg(&goP[1]) + __ldg(&goP[2])) +
                       (1.f - gp) * (__ldg(&poP[3]) + __ldg(&poP[4]));
            float rsum = 0.f;
#pragma unroll
            for (int nf = 0; nf < 4; nf++) {
                int t0 = n0 + wn * 32 + nf * 8 + (lane & 3) * 2;
                float v[2];
#pragma unroll
                for (int j = 0; j < 2; j++) {
                    int t = t0 + j;
                    float w = acc[mf][nf][h * 2 + j] * ow;
                    float loc = fabsf((float)(s - t));
                    w = __fdividef(w, loc + EPS);
                    float e2 = __expf(2.f * w);
                    float th = 1.f - __fdividef(2.f, e2 + 1.f);
                    float r = __expf(th);
                    if (s == t) r = 0.f;
                    v[j] = r;
                }
                rsum += v[0] + v[1];
                size_t off = ((size_t)b * S + s) * S + t0;
                store_pair_split(&g_whi[off], &g_wlo[off], v[0], v[1]);
            }
            // reduce over the 4 lanes (lane&3) holding this row's columns
            rsum += __shfl_xor_sync(0xFFFFFFFFu, rsum, 1);
            rsum += __shfl_xor_sync(0xFFFFFFFFu, rsum, 2);
            if ((lane & 3) == 0) sp[rl][wn] = rsum;
        }
    }
    __syncthreads();
    if (threadIdx.x < 128) {
        int rl = threadIdx.x;
        float t = (sp[rl][0] + sp[rl][1]) + (sp[rl][2] + sp[rl][3]);
        g_rowsum_part[((size_t)b * S + m0 + rl) * 8 + blockIdx.x] = t;
    }
}

// ---------------------------------------------------------------------------
// Rowsum finalize (deterministic fixed-order sum of 8 partials per row)
// ---------------------------------------------------------------------------
__global__ __launch_bounds__(256)
void rowsum_finalize_kernel() {
    int r = blockIdx.x * 256 + threadIdx.x;   // 32768 rows
    const float* p = &g_rowsum_part[(size_t)r * 8];
    float s = 0.f;
#pragma unroll
    for (int i = 0; i < 8; i++) s += p[i];
    g_rowsum[r] = s;
}

// ---------------------------------------------------------------------------
// GEMM3: out[b] = (weights[b] / rowsum) @ x[b]   (B = xT hi/lo)
// ---------------------------------------------------------------------------
__global__ __launch_bounds__(256, 2)
void gemm3_kernel(float* __restrict__ out) {
    const int b  = blockIdx.z;
    const int m0 = blockIdx.y * 128;
    const int n0 = blockIdx.x * 128;

    float acc[4][4][4];
    mma_mainloop(g_whi  + ((size_t)b * S + m0) * 1024, g_wlo  + ((size_t)b * S + m0) * 1024,
                 g_xThi + ((size_t)b * D + n0) * 1024, g_xTlo + ((size_t)b * D + n0) * 1024, acc);

    const int lane = threadIdx.x & 31, wid = threadIdx.x >> 5;
    const int wm = wid & 1, wn = wid >> 1;
    float* Cb = out + (size_t)b * S * D;

#pragma unroll
    for (int mf = 0; mf < 4; mf++)
#pragma unroll
        for (int h = 0; h < 2; h++) {
            int s = m0 + wm * 64 + mf * 16 + (lane >> 2) + h * 8;
            float sc = 1.f / (g_rowsum[b * S + s] + EPS);
#pragma unroll
            for (int nf = 0; nf < 4; nf++) {
                int c0 = n0 + wn * 32 + nf * 8 + (lane & 3) * 2;
                float2 v = make_float2(acc[mf][nf][h * 2 + 0] * sc,
                                       acc[mf][nf][h * 2 + 1] * sc);
                *(float2*)&Cb[(size_t)s * 1024 + c0] = v;
            }
        }
}

// ---------------------------------------------------------------------------
extern "C" void kernel_launch(void* const* d_in, const int* in_sizes, int n_in,
                              void* d_out, int out_size)
{
    const float* x     = (const float*)d_in[0];  // [32,1024,1024]
    const float* W     = (const float*)d_in[1];  // [1024,1024]
    const float* bias  = (const float*)d_in[2];  // [1024]
    const float* go    = (const float*)d_in[3];  // [32,1024,5]
    const float* po    = (const float*)d_in[4];  // [32,1024,5]
    const float* gprob = (const float*)d_in[5];  // scalar
    float* out = (float*)d_out;

    cudaFuncSetAttribute(gemm1_kernel, cudaFuncAttributeMaxDynamicSharedMemorySize, SMEM_DYN);
    cudaFuncSetAttribute(gemm2_kernel, cudaFuncAttributeMaxDynamicSharedMemorySize, SMEM_DYN);
    cudaFuncSetAttribute(gemm3_kernel, cudaFuncAttributeMaxDynamicSharedMemorySize, SMEM_DYN);

    // Launch order chosen so ncu's captured launch (#4) is gemm2_kernel.
    prep_x_kernel<<<dim3(32, 32, BATCH), 256>>>(x);                     // 1
    conv_W_kernel<<<N8W / 256, 256>>>(W);                               // 2
    gemm1_kernel<<<dim3(8, 256), 256, SMEM_DYN>>>(bias);                // 3
    gemm2_kernel<<<dim3(8, 8, BATCH), 256, SMEM_DYN>>>(go, po, gprob);  // 4  <- profiled
    rowsum_finalize_kernel<<<BATCH * S / 256, 256>>>();                 // 5
    gemm3_kernel<<<dim3(8, 8, BATCH), 256, SMEM_DYN>>>(out);            // 6
}